// round 2
// baseline (speedup 1.0000x reference)
#include <cuda_runtime.h>

#define BB   2
#define GG   2
#define CIN  192
#define COUT 384
#define OG   192      // COUT / G
#define HH   48
#define WW   48
#define LL   2304     // H*W
#define KK   25
#define CKK  4800     // CIN * KK
#define REP  96       // CIN / G

#define BM 192
#define BN 64
#define BK 16
#define PAD 4

// 50-bit topo-causal mask per (b, g_out, l): bit (g_in*25 + tap)
__device__ unsigned long long g_mbits[BB * GG * LL];

__global__ void mask_kernel(const int* __restrict__ topo) {
    int idx = blockIdx.x * blockDim.x + threadIdx.x;
    if (idx >= BB * GG * LL) return;
    int l = idx % LL;
    int g = (idx / LL) % GG;
    int b = idx / (LL * GG);
    int y = l / WW, x = l % WW;
    int center = topo[(b * GG + g) * LL + l];
    unsigned long long m = 0ull;
#pragma unroll
    for (int gi = 0; gi < GG; gi++) {
        const int* tg = topo + (b * GG + gi) * LL;
#pragma unroll
        for (int t = 0; t < KK; t++) {
            int yy = y + t / 5 - 2;
            int xx = x + t % 5 - 2;
            // zero padding is always "future" -> false; in-bounds reduces to raw int compare
            if ((unsigned)yy < HH && (unsigned)xx < WW && tg[yy * WW + xx] < center)
                m |= (1ull << (gi * KK + t));
        }
    }
    g_mbits[idx] = m;
}

__device__ __forceinline__ unsigned long long pack_dup(float v) {
    unsigned long long r;
    asm("mov.b64 %0, {%1, %1};" : "=l"(r) : "f"(v));
    return r;
}
__device__ __forceinline__ void ffma2(unsigned long long& d, unsigned long long a,
                                      unsigned long long b) {
    asm("fma.rn.f32x2 %0, %1, %2, %0;" : "+l"(d) : "l"(a), "l"(b));
}
__device__ __forceinline__ float2 as_f2(unsigned long long v) {
    float2 f;
    asm("mov.b64 {%0, %1}, %2;" : "=f"(f.x), "=f"(f.y) : "l"(v));
    return f;
}

// One block: all 192 output channels x 64 pixels for one (b,g).
// Masked unfold of x is gathered on the fly into the B tile.
__global__ __launch_bounds__(256, 1) void conv_gemm_kernel(
    const float* __restrict__ x, const float* __restrict__ dkw,
    const float* __restrict__ dkb, float* __restrict__ out) {
    __shared__ __align__(16) float As[BK][BM + PAD];  // [k][o]
    __shared__ __align__(16) float Bs[BK][BN];        // [k][l]

    const int tid = threadIdx.x;
    const int bg = blockIdx.y;  // b*2 + g
    const int b = bg >> 1, g = bg & 1;
    const int l0 = blockIdx.x * BN;

    const float* wbg = dkw + (size_t)bg * OG * CKK;
    const float* xb = x + (size_t)b * CIN * LL;

    // fixed pixel per thread for B-tile gather
    const int tl = tid & 63;
    const int l = l0 + tl;
    const int ly = l / WW, lx = l % WW;
    const unsigned long long mbits = g_mbits[bg * LL + l];
    const int tib = tid >> 6;  // 0..3

    // compute micro-tile: 12 rows (as 6 packed M-pairs) x 4 cols
    const int tn = (tid & 15) * 4;
    const int tm = (tid >> 4) * 12;

    unsigned long long acc[6][4];
#pragma unroll
    for (int j = 0; j < 6; j++)
#pragma unroll
        for (int n = 0; n < 4; n++) acc[j][n] = 0ull;

    for (int k0 = 0; k0 < CKK; k0 += BK) {
        // ---- A tile: 192 x 16, stored transposed As[k][o] ----
#pragma unroll
        for (int it = 0; it < 3; it++) {
            int idx = tid + it * 256;      // 0..767
            int o = idx >> 2;
            int ip = (idx & 3) * 4;        // k offset
            float4 v = *(const float4*)(wbg + (size_t)o * CKK + k0 + ip);
            As[ip + 0][o] = v.x;
            As[ip + 1][o] = v.y;
            As[ip + 2][o] = v.z;
            As[ip + 3][o] = v.w;
        }
        // ---- B tile: masked unfold gather ----
#pragma unroll
        for (int it = 0; it < 4; it++) {
            int ti = tib + it * 4;
            int i = k0 + ti;
            int c = i / 25;
            int tap = i - c * 25;
            int dy = tap / 5;
            int dx = tap - dy * 5;
            int yy = ly + dy - 2;
            int xx = lx + dx - 2;
            int bit = tap + ((c >= REP) ? KK : 0);
            float v = 0.f;
            if (((mbits >> bit) & 1ull) && (unsigned)yy < HH && (unsigned)xx < WW)
                v = xb[c * LL + yy * WW + xx];
            Bs[ti][tl] = v;
        }
        __syncthreads();

#pragma unroll
        for (int k = 0; k < BK; k++) {
            unsigned long long ap[6];
            const float* arow = &As[k][tm];
#pragma unroll
            for (int q = 0; q < 3; q++) {
                ulonglong2 av = *(const ulonglong2*)(arow + 4 * q);
                ap[2 * q] = av.x;
                ap[2 * q + 1] = av.y;
            }
            float4 bv = *(const float4*)&Bs[k][tn];
            unsigned long long bp[4] = {pack_dup(bv.x), pack_dup(bv.y),
                                        pack_dup(bv.z), pack_dup(bv.w)};
#pragma unroll
            for (int j = 0; j < 6; j++)
#pragma unroll
                for (int n = 0; n < 4; n++) ffma2(acc[j][n], ap[j], bp[n]);
        }
        __syncthreads();
    }

    // ---- epilogue: add bias, write fp32 output ----
    const float* bias = dkb + bg * OG;
    float* outbg = out + (size_t)(b * COUT + g * OG) * LL + l0;
#pragma unroll
    for (int j = 0; j < 6; j++) {
        float2 c0 = as_f2(acc[j][0]);
        float2 c1 = as_f2(acc[j][1]);
        float2 c2 = as_f2(acc[j][2]);
        float2 c3 = as_f2(acc[j][3]);
        int o0 = tm + 2 * j;
        float b0 = bias[o0], b1 = bias[o0 + 1];
        float4 r0 = make_float4(c0.x + b0, c1.x + b0, c2.x + b0, c3.x + b0);
        float4 r1 = make_float4(c0.y + b1, c1.y + b1, c2.y + b1, c3.y + b1);
        *(float4*)(outbg + (size_t)o0 * LL + tn) = r0;
        *(float4*)(outbg + (size_t)(o0 + 1) * LL + tn) = r1;
    }
}

extern "C" void kernel_launch(void* const* d_in, const int* in_sizes, int n_in,
                              void* d_out, int out_size) {
    const float* x = (const float*)d_in[0];
    const int* topo = (const int*)d_in[1];
    const float* dkw = (const float*)d_in[2];
    const float* dkb = (const float*)d_in[3];
    float* out = (float*)d_out;

    mask_kernel<<<(BB * GG * LL + 255) / 256, 256>>>(topo);

    dim3 grid(LL / BN, BB * GG);  // 36 x 4 = 144 blocks (~one wave on 148 SMs)
    conv_gemm_kernel<<<grid, 256>>>(x, dkw, dkb, out);
}

// round 6
// speedup vs baseline: 2.2832x; 2.2832x over previous
#include <cuda_runtime.h>
#include <cstdint>

#define BB   2
#define GG   2
#define CIN  192
#define COUT 384
#define OG   192      // COUT / G
#define HH   48
#define WW   48
#define LL   2304     // H*W
#define KK   25
#define CKK  4800     // CIN * KK
#define REP  96       // CIN / G

#define BM 192
#define BN 64
#define BK 32
#define APAD 4
#define BPAD 4
#define NITER (CKK / BK)   // 150

// 50-bit topo-causal mask per (b, g_out, l): bit (g_in*25 + tap)
// Bit set implies the tap is in-bounds AND strictly-causal.
__device__ unsigned long long g_mbits[BB * GG * LL];

__global__ void mask_kernel(const int* __restrict__ topo) {
    int idx = blockIdx.x * blockDim.x + threadIdx.x;
    if (idx >= BB * GG * LL) return;
    int l = idx % LL;
    int g = (idx / LL) % GG;
    int b = idx / (LL * GG);
    int y = l / WW, x = l % WW;
    int center = topo[(b * GG + g) * LL + l];
    unsigned long long m = 0ull;
#pragma unroll
    for (int gi = 0; gi < GG; gi++) {
        const int* tg = topo + (b * GG + gi) * LL;
#pragma unroll
        for (int t = 0; t < KK; t++) {
            int yy = y + t / 5 - 2;
            int xx = x + t % 5 - 2;
            // zero padding is always "future" -> false; in-bounds reduces to raw int compare
            if ((unsigned)yy < HH && (unsigned)xx < WW && tg[yy * WW + xx] < center)
                m |= (1ull << (gi * KK + t));
        }
    }
    g_mbits[idx] = m;
}

__device__ __forceinline__ uint32_t f2tf(float f) {
    uint32_t u;
    asm("cvt.rna.tf32.f32 %0, %1;" : "=r"(u) : "f"(f));
    return u;
}

__device__ __forceinline__ void mma_tf32(float c[4], const uint32_t a[4],
                                         const uint32_t b[2]) {
    asm volatile(
        "mma.sync.aligned.m16n8k8.row.col.f32.tf32.tf32.f32 "
        "{%0,%1,%2,%3}, {%4,%5,%6,%7}, {%8,%9}, {%0,%1,%2,%3};"
        : "+f"(c[0]), "+f"(c[1]), "+f"(c[2]), "+f"(c[3])
        : "r"(a[0]), "r"(a[1]), "r"(a[2]), "r"(a[3]), "r"(b[0]), "r"(b[1]));
}

// One block: 192 output channels x 64 pixels for one (b,g).
// A = per-image weights (row-major, K contiguous). B = masked unfold of x,
// gathered on the fly (mask bit implies in-bounds). tf32 tensor-core GEMM.
__global__ __launch_bounds__(256, 1) void conv_mma_kernel(
    const float* __restrict__ x, const float* __restrict__ dkw,
    const float* __restrict__ dkb, float* __restrict__ out) {
    __shared__ __align__(16) uint32_t As[BM][BK + APAD];  // [o][k], pad->conflict-free
    __shared__ __align__(16) uint32_t Bs[BK][BN + BPAD];  // [k][l]

    const int tid = threadIdx.x;
    const int lane = tid & 31;
    const int warp = tid >> 5;
    const int bg = blockIdx.y;  // b*2 + g
    const int b = bg >> 1, g = bg & 1;
    const int l0 = blockIdx.x * BN;

    const float* wbg = dkw + (size_t)bg * OG * CKK;
    const float* xb = x + (size_t)b * CIN * LL;

    // B gather mapping: fixed pixel per thread, 8 k-rows per iter
    const int tl = tid & 63;
    const int l = l0 + tl;
    const unsigned long long mbits = g_mbits[bg * LL + l];
    const int rbase = tid >> 6;  // 0..3

    // warp tile: 48 (M) x 32 (N); 3 m16 x 4 n8 mma tiles
    const int wm = (warp >> 1) * 48;
    const int wn = (warp & 1) * 32;
    const int gid = lane >> 2;  // 0..7
    const int tig = lane & 3;   // 0..3

    float acc[3][4][4];
#pragma unroll
    for (int mi = 0; mi < 3; mi++)
#pragma unroll
        for (int ni = 0; ni < 4; ni++)
#pragma unroll
            for (int q = 0; q < 4; q++) acc[mi][ni][q] = 0.f;

    float4 areg[6];
    float breg[8];

    // ---- prologue: prime k0 = 0 ----
#pragma unroll
    for (int it = 0; it < 6; it++) {
        int f = it * 256 + tid;
        int o = f >> 3, kq = f & 7;
        areg[it] = *(const float4*)(wbg + (size_t)o * CKK + kq * 4);
    }
#pragma unroll
    for (int it = 0; it < 8; it++) {
        int i = rbase + it * 4;
        int ci = i / 25;
        int tap = i - ci * 25;
        int off = (tap / 5) * WW + (tap % 5) - (2 * WW + 2);
        int bit = tap + ((ci >= REP) ? KK : 0);
        float v = 0.f;
        if ((mbits >> bit) & 1ull) v = xb[ci * LL + l + off];
        breg[it] = v;
    }

    for (int iter = 0; iter < NITER; iter++) {
        // ---- store staged tiles (with tf32 conversion) ----
#pragma unroll
        for (int it = 0; it < 6; it++) {
            int f = it * 256 + tid;
            int o = f >> 3, kq = f & 7;
            uint4 v;
            v.x = f2tf(areg[it].x);
            v.y = f2tf(areg[it].y);
            v.z = f2tf(areg[it].z);
            v.w = f2tf(areg[it].w);
            *(uint4*)&As[o][kq * 4] = v;
        }
#pragma unroll
        for (int it = 0; it < 8; it++) Bs[rbase + it * 4][tl] = f2tf(breg[it]);
        __syncthreads();

        // ---- prefetch next k-tile (overlaps with mma below) ----
        if (iter + 1 < NITER) {
            int k0 = (iter + 1) * BK;
#pragma unroll
            for (int it = 0; it < 6; it++) {
                int f = it * 256 + tid;
                int o = f >> 3, kq = f & 7;
                areg[it] = *(const float4*)(wbg + (size_t)o * CKK + k0 + kq * 4);
            }
#pragma unroll
            for (int it = 0; it < 8; it++) {
                int i = k0 + rbase + it * 4;
                int ci = i / 25;
                int tap = i - ci * 25;
                int off = (tap / 5) * WW + (tap % 5) - (2 * WW + 2);
                int bit = tap + ((ci >= REP) ? KK : 0);
                float v = 0.f;
                if ((mbits >> bit) & 1ull) v = xb[ci * LL + l + off];
                breg[it] = v;
            }
        }

        // ---- tensor compute: 4 k8 steps x (3x4) mma ----
#pragma unroll
        for (int kk = 0; kk < 4; kk++) {
            int kb = kk * 8;
            uint32_t afr[3][4];
#pragma unroll
            for (int mi = 0; mi < 3; mi++) {
                int r = wm + mi * 16 + gid;
                afr[mi][0] = As[r][kb + tig];
                afr[mi][1] = As[r + 8][kb + tig];
                afr[mi][2] = As[r][kb + tig + 4];
                afr[mi][3] = As[r + 8][kb + tig + 4];
            }
            uint32_t bfr[4][2];
#pragma unroll
            for (int ni = 0; ni < 4; ni++) {
                bfr[ni][0] = Bs[kb + tig][wn + ni * 8 + gid];
                bfr[ni][1] = Bs[kb + tig + 4][wn + ni * 8 + gid];
            }
#pragma unroll
            for (int mi = 0; mi < 3; mi++)
#pragma unroll
                for (int ni = 0; ni < 4; ni++) mma_tf32(acc[mi][ni], afr[mi], bfr[ni]);
        }
        __syncthreads();
    }

    // ---- epilogue: bias + fp32 store ----
    const float* bias = dkb + bg * OG;
    float* outbg = out + (size_t)(b * COUT + g * OG) * LL + l0;
#pragma unroll
    for (int mi = 0; mi < 3; mi++) {
        int r0 = wm + mi * 16 + gid;
        int r1 = r0 + 8;
        float b0 = bias[r0], b1 = bias[r1];
#pragma unroll
        for (int ni = 0; ni < 4; ni++) {
            int col = wn + ni * 8 + tig * 2;
            float2 v0 = make_float2(acc[mi][ni][0] + b0, acc[mi][ni][1] + b0);
            float2 v1 = make_float2(acc[mi][ni][2] + b1, acc[mi][ni][3] + b1);
            *(float2*)(outbg + (size_t)r0 * LL + col) = v0;
            *(float2*)(outbg + (size_t)r1 * LL + col) = v1;
        }
    }
}

extern "C" void kernel_launch(void* const* d_in, const int* in_sizes, int n_in,
                              void* d_out, int out_size) {
    const float* x = (const float*)d_in[0];
    const int* topo = (const int*)d_in[1];
    const float* dkw = (const float*)d_in[2];
    const float* dkb = (const float*)d_in[3];
    float* out = (float*)d_out;

    mask_kernel<<<(BB * GG * LL + 255) / 256, 256>>>(topo);

    dim3 grid(LL / BN, BB * GG);  // 36 x 4 = 144 blocks (~one wave on 148 SMs)
    conv_mma_kernel<<<grid, 256>>>(x, dkw, dkb, out);
}

// round 7
// speedup vs baseline: 2.9990x; 1.3135x over previous
#include <cuda_runtime.h>
#include <cstdint>

#define BB   2
#define GG   2
#define CIN  192
#define COUT 384
#define OG   192      // COUT / G
#define HH   48
#define WW   48
#define LL   2304     // H*W
#define KK   25
#define CKK  4800     // CIN * KK
#define REP  96       // CIN / G

#define BM 192
#define BN 64
#define BK 32
#define ASTR 36       // A row stride (words): bank = 4*gid+tig, conflict-free for frag reads
#define BSTR 72       // B row stride (words): bank = 8*tig+gid, conflict-free (was 68: 2-way)
#define NITER (CKK / BK)   // 150

#define A_ELEMS (BM * ASTR)            // 6912
#define B_ELEMS (BK * BSTR)            // 2304
#define SMEM_BYTES (2 * (A_ELEMS + B_ELEMS) * 4)  // 73728

// 50-bit topo-causal mask per (b, g_out, l): bit (g_in*25 + tap)
// Bit set implies the tap is in-bounds AND strictly-causal.
__device__ unsigned long long g_mbits[BB * GG * LL];

__global__ void mask_kernel(const int* __restrict__ topo) {
    int idx = blockIdx.x * blockDim.x + threadIdx.x;
    if (idx >= BB * GG * LL) return;
    int l = idx % LL;
    int g = (idx / LL) % GG;
    int b = idx / (LL * GG);
    int y = l / WW, x = l % WW;
    int center = topo[(b * GG + g) * LL + l];
    unsigned long long m = 0ull;
#pragma unroll
    for (int gi = 0; gi < GG; gi++) {
        const int* tg = topo + (b * GG + gi) * LL;
#pragma unroll
        for (int t = 0; t < KK; t++) {
            int yy = y + t / 5 - 2;
            int xx = x + t % 5 - 2;
            // zero padding is always "future" -> false; in-bounds is raw int compare
            if ((unsigned)yy < HH && (unsigned)xx < WW && tg[yy * WW + xx] < center)
                m |= (1ull << (gi * KK + t));
        }
    }
    g_mbits[idx] = m;
}

__device__ __forceinline__ void mma_tf32(float c[4], const uint32_t a[4],
                                         const uint32_t b[2]) {
    asm volatile(
        "mma.sync.aligned.m16n8k8.row.col.f32.tf32.tf32.f32 "
        "{%0,%1,%2,%3}, {%4,%5,%6,%7}, {%8,%9}, {%0,%1,%2,%3};"
        : "+f"(c[0]), "+f"(c[1]), "+f"(c[2]), "+f"(c[3])
        : "r"(a[0]), "r"(a[1]), "r"(a[2]), "r"(a[3]), "r"(b[0]), "r"(b[1]));
}

// One block: 192 output channels x 64 pixels for one (b,g).
// A = per-image weights, B = masked unfold of x gathered on the fly.
// Raw fp32 bits fed to tf32 mma (HW truncates mantissa) -> zero cvt cost.
// Double-buffered smem, ONE __syncthreads per k-iteration.
__global__ __launch_bounds__(256, 1) void conv_mma_kernel(
    const float* __restrict__ x, const float* __restrict__ dkw,
    const float* __restrict__ dkb, float* __restrict__ out) {
    extern __shared__ float smem[];
    float* Asm = smem;                    // [2][BM][ASTR]
    float* Bsm = smem + 2 * A_ELEMS;      // [2][BK][BSTR]

    const int tid = threadIdx.x;
    const int lane = tid & 31;
    const int warp = tid >> 5;
    const int bg = blockIdx.y;  // b*2 + g
    const int b = bg >> 1;
    const int l0 = blockIdx.x * BN;

    const float* wbg = dkw + (size_t)bg * OG * CKK;
    const float* xb = x + (size_t)b * CIN * LL;

    // B gather mapping: fixed pixel per thread, 8 k-rows per iter
    const int tl = tid & 63;
    const int l = l0 + tl;
    const unsigned long long mbits = g_mbits[bg * LL + l];
    const int rbase = tid >> 6;  // 0..3

    // A load mapping: fixed (o, kq) per thread
    const int ao0 = tid >> 3;        // +32 per it
    const int akq = (tid & 7) * 4;

    // warp tile: 48 (M) x 32 (N); 3 m16 x 4 n8 mma tiles
    const int wm = (warp >> 1) * 48;
    const int wn = (warp & 1) * 32;
    const int gid = lane >> 2;  // 0..7
    const int tig = lane & 3;   // 0..3

    float acc[3][4][4];
#pragma unroll
    for (int mi = 0; mi < 3; mi++)
#pragma unroll
        for (int ni = 0; ni < 4; ni++)
#pragma unroll
            for (int q = 0; q < 4; q++) acc[mi][ni][q] = 0.f;

    float4 areg[6];
    float breg[8];

    // ---- prologue: prime k0 = 0 ----
#pragma unroll
    for (int it = 0; it < 6; it++)
        areg[it] = *(const float4*)(wbg + (size_t)(ao0 + it * 32) * CKK + akq);
#pragma unroll
    for (int it = 0; it < 8; it++) {
        int i = rbase + it * 4;
        int ci = i / 25;
        int tap = i - ci * 25;
        int off = (tap / 5) * WW + (tap % 5) - (2 * WW + 2);
        int bit = tap + ((ci >= REP) ? KK : 0);
        float v = 0.f;
        if ((mbits >> bit) & 1ull) v = xb[ci * LL + l + off];
        breg[it] = v;
    }

#pragma unroll 2
    for (int iter = 0; iter < NITER; iter++) {
        const int s = iter & 1;
        float* As = Asm + s * A_ELEMS;
        float* Bs = Bsm + s * B_ELEMS;

        // ---- store staged tiles (raw fp32 bits) ----
#pragma unroll
        for (int it = 0; it < 6; it++)
            *(float4*)(As + (ao0 + it * 32) * ASTR + akq) = areg[it];
#pragma unroll
        for (int it = 0; it < 8; it++)
            Bs[(rbase + it * 4) * BSTR + tl] = breg[it];
        __syncthreads();  // single barrier: STS(i+1) targets the other buffer

        // ---- prefetch next k-tile into regs (overlaps with mma below) ----
        if (iter + 1 < NITER) {
            int k0 = (iter + 1) * BK;
#pragma unroll
            for (int it = 0; it < 6; it++)
                areg[it] = *(const float4*)(wbg + (size_t)(ao0 + it * 32) * CKK + k0 + akq);
#pragma unroll
            for (int it = 0; it < 8; it++) {
                int i = k0 + rbase + it * 4;
                int ci = i / 25;
                int tap = i - ci * 25;
                int off = (tap / 5) * WW + (tap % 5) - (2 * WW + 2);
                int bit = tap + ((ci >= REP) ? KK : 0);
                float v = 0.f;
                if ((mbits >> bit) & 1ull) v = xb[ci * LL + l + off];
                breg[it] = v;
            }
        }

        // ---- tensor compute: 4 k8 steps x (3x4) mma ----
        const uint32_t* Au = (const uint32_t*)As;
        const uint32_t* Bu = (const uint32_t*)Bs;
#pragma unroll
        for (int kk = 0; kk < 4; kk++) {
            int kb = kk * 8;
            uint32_t afr[3][4];
#pragma unroll
            for (int mi = 0; mi < 3; mi++) {
                int r = wm + mi * 16 + gid;
                afr[mi][0] = Au[r * ASTR + kb + tig];
                afr[mi][1] = Au[(r + 8) * ASTR + kb + tig];
                afr[mi][2] = Au[r * ASTR + kb + tig + 4];
                afr[mi][3] = Au[(r + 8) * ASTR + kb + tig + 4];
            }
            uint32_t bfr[4][2];
#pragma unroll
            for (int ni = 0; ni < 4; ni++) {
                int col = wn + ni * 8 + gid;
                bfr[ni][0] = Bu[(kb + tig) * BSTR + col];
                bfr[ni][1] = Bu[(kb + tig + 4) * BSTR + col];
            }
#pragma unroll
            for (int mi = 0; mi < 3; mi++)
#pragma unroll
                for (int ni = 0; ni < 4; ni++) mma_tf32(acc[mi][ni], afr[mi], bfr[ni]);
        }
    }

    // ---- epilogue: bias + fp32 store ----
    const int g = bg & 1;
    const float* bias = dkb + bg * OG;
    float* outbg = out + (size_t)(b * COUT + g * OG) * LL + l0;
#pragma unroll
    for (int mi = 0; mi < 3; mi++) {
        int r0 = wm + mi * 16 + gid;
        int r1 = r0 + 8;
        float b0 = bias[r0], b1 = bias[r1];
#pragma unroll
        for (int ni = 0; ni < 4; ni++) {
            int col = wn + ni * 8 + tig * 2;
            float2 v0 = make_float2(acc[mi][ni][0] + b0, acc[mi][ni][1] + b0);
            float2 v1 = make_float2(acc[mi][ni][2] + b1, acc[mi][ni][3] + b1);
            *(float2*)(outbg + (size_t)r0 * LL + col) = v0;
            *(float2*)(outbg + (size_t)r1 * LL + col) = v1;
        }
    }
}

extern "C" void kernel_launch(void* const* d_in, const int* in_sizes, int n_in,
                              void* d_out, int out_size) {
    const float* x = (const float*)d_in[0];
    const int* topo = (const int*)d_in[1];
    const float* dkw = (const float*)d_in[2];
    const float* dkb = (const float*)d_in[3];
    float* out = (float*)d_out;

    static bool attr_set = false;
    if (!attr_set) {
        cudaFuncSetAttribute(conv_mma_kernel,
                             cudaFuncAttributeMaxDynamicSharedMemorySize, SMEM_BYTES);
        attr_set = true;
    }

    mask_kernel<<<(BB * GG * LL + 255) / 256, 256>>>(topo);

    dim3 grid(LL / BN, BB * GG);  // 36 x 4 = 144 blocks (~one wave on 148 SMs)
    conv_mma_kernel<<<grid, 256, SMEM_BYTES>>>(x, dkw, dkb, out);
}

// round 8
// speedup vs baseline: 3.2891x; 1.0968x over previous
#include <cuda_runtime.h>
#include <cstdint>

#define BB   2
#define GG   2
#define CIN  192
#define COUT 384
#define OG   192      // COUT / G
#define HH   48
#define WW   48
#define LL   2304     // H*W
#define KK   25
#define CKK  4800     // CIN * KK
#define REP  96       // CIN / G

#define BM 192
#define BN 64
#define BK 32
#define ASTR 36       // A row stride (words): frag bank = 4*gid+tig, conflict-free
#define BSTR 72       // B row stride (words): frag bank = 8*tig+gid, conflict-free
#define NKT   (CKK / BK)   // 150 k-tiles
#define JITER (NKT / 2)    // 75 per team

#define A_ELEMS (BM * ASTR)              // 6912 words
#define B_ELEMS (BK * BSTR)              // 2304 words
#define STAGE_ELEMS (A_ELEMS + B_ELEMS)  // 9216 words
#define SMEM_BYTES (2 * 3 * STAGE_ELEMS * 4)  // 221184 B (2 teams x 3 stages)

// 50-bit topo-causal mask per (b, g_out, l): bit (g_in*25 + tap)
// Bit set implies the tap is in-bounds AND strictly-causal.
__device__ unsigned long long g_mbits[BB * GG * LL];

__global__ void mask_kernel(const int* __restrict__ topo) {
    int idx = blockIdx.x * blockDim.x + threadIdx.x;
    if (idx >= BB * GG * LL) return;
    int l = idx % LL;
    int g = (idx / LL) % GG;
    int b = idx / (LL * GG);
    int y = l / WW, x = l % WW;
    int center = topo[(b * GG + g) * LL + l];
    unsigned long long m = 0ull;
#pragma unroll
    for (int gi = 0; gi < GG; gi++) {
        const int* tg = topo + (b * GG + gi) * LL;
#pragma unroll
        for (int t = 0; t < KK; t++) {
            int yy = y + t / 5 - 2;
            int xx = x + t % 5 - 2;
            // zero padding is always "future" -> false; in-bounds is raw int compare
            if ((unsigned)yy < HH && (unsigned)xx < WW && tg[yy * WW + xx] < center)
                m |= (1ull << (gi * KK + t));
        }
    }
    g_mbits[idx] = m;
}

__device__ __forceinline__ void mma_tf32(float c[4], const uint32_t a[4],
                                         const uint32_t b[2]) {
    asm volatile(
        "mma.sync.aligned.m16n8k8.row.col.f32.tf32.tf32.f32 "
        "{%0,%1,%2,%3}, {%4,%5,%6,%7}, {%8,%9}, {%0,%1,%2,%3};"
        : "+f"(c[0]), "+f"(c[1]), "+f"(c[2]), "+f"(c[3])
        : "r"(a[0]), "r"(a[1]), "r"(a[2]), "r"(a[3]), "r"(b[0]), "r"(b[1]));
}

__device__ __forceinline__ void cp16(uint32_t dst, const float* src) {
    asm volatile("cp.async.cg.shared.global [%0], [%1], 16;"
                 :: "r"(dst), "l"(src) : "memory");
}
// 4-byte cp.async with runtime src-size (0 -> pure zero-fill, no gmem read)
__device__ __forceinline__ void cp4z(uint32_t dst, const float* src, uint32_t sz) {
    asm volatile("cp.async.ca.shared.global [%0], [%1], 4, %2;"
                 :: "r"(dst), "l"(src), "r"(sz) : "memory");
}
__device__ __forceinline__ void cp_commit() {
    asm volatile("cp.async.commit_group;" ::: "memory");
}
template <int N>
__device__ __forceinline__ void cp_wait() {
    asm volatile("cp.async.wait_group %0;" :: "n"(N) : "memory");
}

// Prefetch one k-tile (A: 192x32 dense weights, B: 32x64 masked gather) via cp.async.
__device__ __forceinline__ void prefetch_stage(
    float* stage, const float* wbg, const float* xb, int k0,
    int ao0, int akq, int rbase, int tl, int l, unsigned long long mbits) {
    uint32_t as_u = (uint32_t)__cvta_generic_to_shared(stage);
    uint32_t bs_u = (uint32_t)__cvta_generic_to_shared(stage + A_ELEMS);
#pragma unroll
    for (int it = 0; it < 6; it++) {
        int o = ao0 + it * 32;
        cp16(as_u + (uint32_t)((o * ASTR + akq) << 2),
             wbg + (size_t)o * CKK + k0 + akq);
    }
#pragma unroll
    for (int it = 0; it < 8; it++) {
        int r = rbase + it * 4;
        int i = k0 + r;
        int ci = i / 25;
        int tap = i - ci * 25;
        int off = (tap / 5) * WW + (tap % 5) - (2 * WW + 2);
        int bit = tap + ((ci >= REP) ? KK : 0);
        uint32_t sz = (uint32_t)((mbits >> bit) & 1ull) << 2;  // 4 or 0
        cp4z(bs_u + (uint32_t)((r * BSTR + tl) << 2), xb + ci * LL + l + off, sz);
    }
}

// One block: 192 out-channels x 64 pixels for one (b,g). 512 threads = 2 teams
// of 8 warps; team t handles k-tiles t, t+2, ... (split-K x2), each with its own
// triple-buffered cp.async pipeline. Cross-team reduce via smem at the end.
__global__ __launch_bounds__(512, 1) void conv_mma_kernel(
    const float* __restrict__ x, const float* __restrict__ dkw,
    const float* __restrict__ dkb, float* __restrict__ out) {
    extern __shared__ float smem[];

    const int tid = threadIdx.x;
    const int team = tid >> 8;
    const int ttid = tid & 255;
    const int lane = tid & 31;
    const int twarp = ttid >> 5;  // 0..7
    const int bg = blockIdx.y;    // b*2 + g
    const int b = bg >> 1;
    const int l0 = blockIdx.x * BN;

    const float* wbg = dkw + (size_t)bg * OG * CKK;
    const float* xb = x + (size_t)b * CIN * LL;

    // B gather mapping: fixed pixel per thread, 8 k-rows per tile
    const int tl = ttid & 63;
    const int l = l0 + tl;
    const unsigned long long mbits = g_mbits[bg * LL + l];
    const int rbase = ttid >> 6;  // 0..3

    // A load mapping
    const int ao0 = ttid >> 3;        // 0..31, +32 per chunk
    const int akq = (ttid & 7) * 4;

    // warp tile: 48 (M) x 32 (N); 3 m16 x 4 n8 mma tiles
    const int wm = (twarp >> 1) * 48;
    const int wn = (twarp & 1) * 32;
    const int gid = lane >> 2;
    const int tig = lane & 3;

    float* Tb = smem + team * (3 * STAGE_ELEMS);

    float acc[3][4][4];
#pragma unroll
    for (int mi = 0; mi < 3; mi++)
#pragma unroll
        for (int ni = 0; ni < 4; ni++)
#pragma unroll
            for (int q = 0; q < 4; q++) acc[mi][ni][q] = 0.f;

    // ---- prologue: prime stages 0 and 1 ----
    prefetch_stage(Tb, wbg, xb, team * BK, ao0, akq, rbase, tl, l, mbits);
    cp_commit();
    prefetch_stage(Tb + STAGE_ELEMS, wbg, xb, (team + 2) * BK, ao0, akq, rbase, tl, l, mbits);
    cp_commit();

#pragma unroll 3
    for (int j = 0; j < JITER; j++) {
        cp_wait<1>();       // stage j%3 complete (<=1 group outstanding)
        __syncthreads();    // publish; also: all warps done reading stage (j+2)%3
        if (j + 2 < JITER)
            prefetch_stage(Tb + (size_t)((j + 2) % 3) * STAGE_ELEMS, wbg, xb,
                           (team + 2 * (j + 2)) * BK, ao0, akq, rbase, tl, l, mbits);
        cp_commit();        // always commit (empty at tail) to keep group counts aligned

        const uint32_t* Au = (const uint32_t*)(Tb + (size_t)(j % 3) * STAGE_ELEMS);
        const uint32_t* Bu = Au + A_ELEMS;
#pragma unroll
        for (int kk = 0; kk < 4; kk++) {
            int kb = kk * 8;
            uint32_t afr[3][4];
#pragma unroll
            for (int mi = 0; mi < 3; mi++) {
                int r = wm + mi * 16 + gid;
                afr[mi][0] = Au[r * ASTR + kb + tig];
                afr[mi][1] = Au[(r + 8) * ASTR + kb + tig];
                afr[mi][2] = Au[r * ASTR + kb + tig + 4];
                afr[mi][3] = Au[(r + 8) * ASTR + kb + tig + 4];
            }
            uint32_t bfr[4][2];
#pragma unroll
            for (int ni = 0; ni < 4; ni++) {
                int col = wn + ni * 8 + gid;
                bfr[ni][0] = Bu[(kb + tig) * BSTR + col];
                bfr[ni][1] = Bu[(kb + tig + 4) * BSTR + col];
            }
#pragma unroll
            for (int mi = 0; mi < 3; mi++)
#pragma unroll
                for (int ni = 0; ni < 4; ni++) mma_tf32(acc[mi][ni], afr[mi], bfr[ni]);
        }
    }

    // ---- drain async copies, then cross-team reduction through smem ----
    cp_wait<0>();
    __syncthreads();

    float* red = smem;  // reuse stage memory: 256 threads * 52 words
    if (team == 1) {
#pragma unroll
        for (int mi = 0; mi < 3; mi++)
#pragma unroll
            for (int ni = 0; ni < 4; ni++)
                *(float4*)(red + ttid * 52 + (mi * 4 + ni) * 4) =
                    make_float4(acc[mi][ni][0], acc[mi][ni][1],
                                acc[mi][ni][2], acc[mi][ni][3]);
    }
    __syncthreads();

    if (team == 0) {
        const int g = bg & 1;
        const float* bias = dkb + bg * OG;
        float* outbg = out + (size_t)(b * COUT + g * OG) * LL + l0;
#pragma unroll
        for (int mi = 0; mi < 3; mi++) {
            int r0 = wm + mi * 16 + gid;
            int r1 = r0 + 8;
            float b0 = bias[r0], b1 = bias[r1];
#pragma unroll
            for (int ni = 0; ni < 4; ni++) {
                float4 o2 = *(const float4*)(red + ttid * 52 + (mi * 4 + ni) * 4);
                int col = wn + ni * 8 + tig * 2;
                float2 v0 = make_float2(acc[mi][ni][0] + o2.x + b0,
                                        acc[mi][ni][1] + o2.y + b0);
                float2 v1 = make_float2(acc[mi][ni][2] + o2.z + b1,
                                        acc[mi][ni][3] + o2.w + b1);
                *(float2*)(outbg + (size_t)r0 * LL + col) = v0;
                *(float2*)(outbg + (size_t)r1 * LL + col) = v1;
            }
        }
    }
}

extern "C" void kernel_launch(void* const* d_in, const int* in_sizes, int n_in,
                              void* d_out, int out_size) {
    const float* x = (const float*)d_in[0];
    const int* topo = (const int*)d_in[1];
    const float* dkw = (const float*)d_in[2];
    const float* dkb = (const float*)d_in[3];
    float* out = (float*)d_out;

    static bool attr_set = false;
    if (!attr_set) {
        cudaFuncSetAttribute(conv_mma_kernel,
                             cudaFuncAttributeMaxDynamicSharedMemorySize, SMEM_BYTES);
        attr_set = true;
    }

    mask_kernel<<<(BB * GG * LL + 255) / 256, 256>>>(topo);

    dim3 grid(LL / BN, BB * GG);  // 36 x 4 = 144 blocks (~one wave on 148 SMs)
    conv_mma_kernel<<<grid, 512, SMEM_BYTES>>>(x, dkw, dkb, out);
}